// round 1
// baseline (speedup 1.0000x reference)
#include <cuda_runtime.h>
#include <cstdint>

// ---------------------------------------------------------------------------
// Problem constants (from reference):
// B=2, NV=8192, C=256, NP=2048, NS=32, H=4, DH=64
// ---------------------------------------------------------------------------
namespace {
constexpr int B_  = 2;
constexpr int NV_ = 8192;
constexpr int C_  = 256;
constexpr int NP2 = 2048;
constexpr int NS_ = 32;
constexpr int H_  = 4;
constexpr int DH_ = 64;
constexpr int MKV = NP2 * NS_;     // 65536 rows per batch for K/V projection
constexpr int MQ  = B_ * NV_;      // 16384 rows for Q / O projection
}

// Scratch (static __device__ globals: allocation-free per harness rules)
__device__ float g_K[(size_t)B_ * H_ * NP2 * NS_ * DH_];   // [B,H,NP,NS,DH] 134 MB
__device__ float g_V[(size_t)B_ * H_ * NP2 * NS_ * DH_];   // 134 MB
__device__ float g_Q[(size_t)B_ * H_ * NV_ * DH_];         // [B,H,NV,DH] 16.8 MB
__device__ float g_Ao[(size_t)B_ * NV_ * C_];              // [B,NV,C]    16.8 MB

// ---------------------------------------------------------------------------
// GEMM 1: K/V projection.  A is K-major: A[b][c][m]  (m = p*NS+s), shape
// [B, C, MKV].  out[m, n] = sum_c (A1 [+A2])[c, m] * W[n, c] + bias[n]
// Epilogue scatters to [B, H, NP, NS, DH] with n = h*DH + d.
// Tile 128x128x16, 256 threads, 8x8 per thread (2x2 quadrants of 4x4),
// double-buffered smem.
// ---------------------------------------------------------------------------
__global__ void __launch_bounds__(256, 2)
kv_proj_kernel(const float* __restrict__ gf,
               const float* __restrict__ kp,
               const float* __restrict__ W,
               const float* __restrict__ bias,
               float* __restrict__ out,
               int addKp)
{
    __shared__ __align__(16) float As[2][16][128];
    __shared__ __align__(16) float Bs[2][16][128];

    const int b   = blockIdx.z;
    const int m0  = blockIdx.x * 128;
    const int n0  = blockIdx.y * 128;
    const int tid = threadIdx.x;
    const int tx  = tid & 15;
    const int ty  = tid >> 4;

    const float* A1 = gf + (size_t)b * C_ * MKV;
    const float* A2 = kp + (size_t)b * C_ * MKV;

    // A-tile load mapping (K-major source: contiguous in m)
    const int lk = tid >> 5;           // 0..7
    const int lm = (tid & 31) << 2;    // 0..124
    // B-tile load mapping (W row-major [N][K], contiguous in k)
    const int bn = tid >> 1;           // 0..127
    const int bk = (tid & 1) << 3;     // 0 or 8

    float acc[8][8];
#pragma unroll
    for (int i = 0; i < 8; i++)
#pragma unroll
        for (int j = 0; j < 8; j++) acc[i][j] = 0.f;

    // ---- preload chunk 0 ----
    {
        float4 a0 = *(const float4*)&A1[(size_t)lk * MKV + m0 + lm];
        float4 a1 = *(const float4*)&A1[(size_t)(lk + 8) * MKV + m0 + lm];
        if (addKp) {
            float4 p0 = *(const float4*)&A2[(size_t)lk * MKV + m0 + lm];
            float4 p1 = *(const float4*)&A2[(size_t)(lk + 8) * MKV + m0 + lm];
            a0.x += p0.x; a0.y += p0.y; a0.z += p0.z; a0.w += p0.w;
            a1.x += p1.x; a1.y += p1.y; a1.z += p1.z; a1.w += p1.w;
        }
        *(float4*)&As[0][lk][lm]     = a0;
        *(float4*)&As[0][lk + 8][lm] = a1;
        float4 w0 = *(const float4*)&W[(size_t)(n0 + bn) * C_ + bk];
        float4 w1 = *(const float4*)&W[(size_t)(n0 + bn) * C_ + bk + 4];
        Bs[0][bk + 0][bn] = w0.x; Bs[0][bk + 1][bn] = w0.y;
        Bs[0][bk + 2][bn] = w0.z; Bs[0][bk + 3][bn] = w0.w;
        Bs[0][bk + 4][bn] = w1.x; Bs[0][bk + 5][bn] = w1.y;
        Bs[0][bk + 6][bn] = w1.z; Bs[0][bk + 7][bn] = w1.w;
    }
    __syncthreads();

    const int NKC = C_ / 16;   // 16 chunks
    for (int kc = 0; kc < NKC; kc++) {
        const int buf = kc & 1;
        float4 na0, na1, nw0, nw1;
        if (kc + 1 < NKC) {
            const int k0 = (kc + 1) * 16;
            na0 = *(const float4*)&A1[(size_t)(k0 + lk) * MKV + m0 + lm];
            na1 = *(const float4*)&A1[(size_t)(k0 + lk + 8) * MKV + m0 + lm];
            if (addKp) {
                float4 p0 = *(const float4*)&A2[(size_t)(k0 + lk) * MKV + m0 + lm];
                float4 p1 = *(const float4*)&A2[(size_t)(k0 + lk + 8) * MKV + m0 + lm];
                na0.x += p0.x; na0.y += p0.y; na0.z += p0.z; na0.w += p0.w;
                na1.x += p1.x; na1.y += p1.y; na1.z += p1.z; na1.w += p1.w;
            }
            nw0 = *(const float4*)&W[(size_t)(n0 + bn) * C_ + k0 + bk];
            nw1 = *(const float4*)&W[(size_t)(n0 + bn) * C_ + k0 + bk + 4];
        }
#pragma unroll
        for (int k = 0; k < 16; k++) {
            float4 a0 = *(const float4*)&As[buf][k][ty * 4];
            float4 a1 = *(const float4*)&As[buf][k][ty * 4 + 64];
            float4 b0 = *(const float4*)&Bs[buf][k][tx * 4];
            float4 b1 = *(const float4*)&Bs[buf][k][tx * 4 + 64];
            float av[8] = {a0.x, a0.y, a0.z, a0.w, a1.x, a1.y, a1.z, a1.w};
            float bv[8] = {b0.x, b0.y, b0.z, b0.w, b1.x, b1.y, b1.z, b1.w};
#pragma unroll
            for (int i = 0; i < 8; i++)
#pragma unroll
                for (int j = 0; j < 8; j++)
                    acc[i][j] = fmaf(av[i], bv[j], acc[i][j]);
        }
        if (kc + 1 < NKC) {
            const int nb = buf ^ 1;
            *(float4*)&As[nb][lk][lm]     = na0;
            *(float4*)&As[nb][lk + 8][lm] = na1;
            Bs[nb][bk + 0][bn] = nw0.x; Bs[nb][bk + 1][bn] = nw0.y;
            Bs[nb][bk + 2][bn] = nw0.z; Bs[nb][bk + 3][bn] = nw0.w;
            Bs[nb][bk + 4][bn] = nw1.x; Bs[nb][bk + 5][bn] = nw1.y;
            Bs[nb][bk + 6][bn] = nw1.z; Bs[nb][bk + 7][bn] = nw1.w;
            __syncthreads();
        }
    }

    // ---- epilogue: bias + scatter to [B,H,NP,NS,DH] ----
#pragma unroll
    for (int qi = 0; qi < 2; qi++)
#pragma unroll
        for (int r = 0; r < 4; r++) {
            const int mrow = m0 + qi * 64 + ty * 4 + r;
            const int p = mrow >> 5;
            const int s = mrow & 31;
#pragma unroll
            for (int qj = 0; qj < 2; qj++) {
                const int ncol = n0 + qj * 64 + tx * 4;
                const int hh = ncol >> 6;
                const int d  = ncol & 63;
                float4 o;
                o.x = acc[qi * 4 + r][qj * 4 + 0] + bias[ncol + 0];
                o.y = acc[qi * 4 + r][qj * 4 + 1] + bias[ncol + 1];
                o.z = acc[qi * 4 + r][qj * 4 + 2] + bias[ncol + 2];
                o.w = acc[qi * 4 + r][qj * 4 + 3] + bias[ncol + 3];
                *(float4*)&out[((((size_t)b * H_ + hh) * NP2 + p) * NS_ + s) * DH_ + d] = o;
            }
        }
}

// ---------------------------------------------------------------------------
// GEMM 2: row-major A [M][256] @ W^T + bias.
// mode 0: Q projection, epilogue permutes to [B,H,NV,DH]
// mode 1: O projection, plain [M][256] output
// ---------------------------------------------------------------------------
__global__ void __launch_bounds__(256, 2)
rm_gemm_kernel(const float* __restrict__ A,
               const float* __restrict__ W,
               const float* __restrict__ bias,
               float* __restrict__ out,
               int mode)
{
    __shared__ __align__(16) float As[2][16][128];
    __shared__ __align__(16) float Bs[2][16][128];

    const int m0  = blockIdx.x * 128;
    const int n0  = blockIdx.y * 128;
    const int tid = threadIdx.x;
    const int tx  = tid & 15;
    const int ty  = tid >> 4;

    // A row-major load mapping (transpose into smem)
    const int am = tid >> 1;         // 0..127
    const int ak = (tid & 1) << 3;   // 0 or 8
    // B load mapping
    const int bn = tid >> 1;
    const int bk = (tid & 1) << 3;

    float acc[8][8];
#pragma unroll
    for (int i = 0; i < 8; i++)
#pragma unroll
        for (int j = 0; j < 8; j++) acc[i][j] = 0.f;

    {
        float4 a0 = *(const float4*)&A[(size_t)(m0 + am) * C_ + ak];
        float4 a1 = *(const float4*)&A[(size_t)(m0 + am) * C_ + ak + 4];
        As[0][ak + 0][am] = a0.x; As[0][ak + 1][am] = a0.y;
        As[0][ak + 2][am] = a0.z; As[0][ak + 3][am] = a0.w;
        As[0][ak + 4][am] = a1.x; As[0][ak + 5][am] = a1.y;
        As[0][ak + 6][am] = a1.z; As[0][ak + 7][am] = a1.w;
        float4 w0 = *(const float4*)&W[(size_t)(n0 + bn) * C_ + bk];
        float4 w1 = *(const float4*)&W[(size_t)(n0 + bn) * C_ + bk + 4];
        Bs[0][bk + 0][bn] = w0.x; Bs[0][bk + 1][bn] = w0.y;
        Bs[0][bk + 2][bn] = w0.z; Bs[0][bk + 3][bn] = w0.w;
        Bs[0][bk + 4][bn] = w1.x; Bs[0][bk + 5][bn] = w1.y;
        Bs[0][bk + 6][bn] = w1.z; Bs[0][bk + 7][bn] = w1.w;
    }
    __syncthreads();

    const int NKC = C_ / 16;
    for (int kc = 0; kc < NKC; kc++) {
        const int buf = kc & 1;
        float4 na0, na1, nw0, nw1;
        if (kc + 1 < NKC) {
            const int k0 = (kc + 1) * 16;
            na0 = *(const float4*)&A[(size_t)(m0 + am) * C_ + k0 + ak];
            na1 = *(const float4*)&A[(size_t)(m0 + am) * C_ + k0 + ak + 4];
            nw0 = *(const float4*)&W[(size_t)(n0 + bn) * C_ + k0 + bk];
            nw1 = *(const float4*)&W[(size_t)(n0 + bn) * C_ + k0 + bk + 4];
        }
#pragma unroll
        for (int k = 0; k < 16; k++) {
            float4 a0 = *(const float4*)&As[buf][k][ty * 4];
            float4 a1 = *(const float4*)&As[buf][k][ty * 4 + 64];
            float4 b0 = *(const float4*)&Bs[buf][k][tx * 4];
            float4 b1 = *(const float4*)&Bs[buf][k][tx * 4 + 64];
            float av[8] = {a0.x, a0.y, a0.z, a0.w, a1.x, a1.y, a1.z, a1.w};
            float bv[8] = {b0.x, b0.y, b0.z, b0.w, b1.x, b1.y, b1.z, b1.w};
#pragma unroll
            for (int i = 0; i < 8; i++)
#pragma unroll
                for (int j = 0; j < 8; j++)
                    acc[i][j] = fmaf(av[i], bv[j], acc[i][j]);
        }
        if (kc + 1 < NKC) {
            const int nb = buf ^ 1;
            As[nb][ak + 0][am] = na0.x; As[nb][ak + 1][am] = na0.y;
            As[nb][ak + 2][am] = na0.z; As[nb][ak + 3][am] = na0.w;
            As[nb][ak + 4][am] = na1.x; As[nb][ak + 5][am] = na1.y;
            As[nb][ak + 6][am] = na1.z; As[nb][ak + 7][am] = na1.w;
            Bs[nb][bk + 0][bn] = nw0.x; Bs[nb][bk + 1][bn] = nw0.y;
            Bs[nb][bk + 2][bn] = nw0.z; Bs[nb][bk + 3][bn] = nw0.w;
            Bs[nb][bk + 4][bn] = nw1.x; Bs[nb][bk + 5][bn] = nw1.y;
            Bs[nb][bk + 6][bn] = nw1.z; Bs[nb][bk + 7][bn] = nw1.w;
            __syncthreads();
        }
    }

#pragma unroll
    for (int qi = 0; qi < 2; qi++)
#pragma unroll
        for (int r = 0; r < 4; r++) {
            const int mrow = m0 + qi * 64 + ty * 4 + r;
#pragma unroll
            for (int qj = 0; qj < 2; qj++) {
                const int ncol = n0 + qj * 64 + tx * 4;
                float4 o;
                o.x = acc[qi * 4 + r][qj * 4 + 0] + bias[ncol + 0];
                o.y = acc[qi * 4 + r][qj * 4 + 1] + bias[ncol + 1];
                o.z = acc[qi * 4 + r][qj * 4 + 2] + bias[ncol + 2];
                o.w = acc[qi * 4 + r][qj * 4 + 3] + bias[ncol + 3];
                if (mode == 0) {
                    // Q: [B,H,NV,DH]
                    const int bb = mrow >> 13;        // / NV
                    const int nv = mrow & (NV_ - 1);
                    const int hh = ncol >> 6;
                    const int d  = ncol & 63;
                    *(float4*)&out[(((size_t)(bb * H_ + hh)) * NV_ + nv) * DH_ + d] = o;
                } else {
                    *(float4*)&out[(size_t)mrow * C_ + ncol] = o;
                }
            }
        }
}

// ---------------------------------------------------------------------------
// Attention: one warp per (b,h,nv) query.  NS=32 -> one score per lane.
// K/V pages are contiguous 8 KB blocks in [B,H,NP,NS,DH]; consecutive blocks
// share (b,h) so K+V (33.5 MB) stays L2-resident per (b,h).
// ---------------------------------------------------------------------------
__global__ void __launch_bounds__(256)
attn_kernel(const int* __restrict__ nidx, float* __restrict__ outA)
{
    __shared__ __align__(16) float sq[8][64];
    const int w    = threadIdx.x >> 5;
    const int lane = threadIdx.x & 31;
    const int qid  = blockIdx.x * 8 + w;

    const int b  = qid >> 15;          // / (H*NV)
    const int h  = (qid >> 13) & 3;    // / NV % H
    const int nv = qid & (NV_ - 1);

    const float* qp = g_Q + (size_t)qid * DH_;
    sq[w][lane]      = qp[lane];
    sq[w][lane + 32] = qp[lane + 32];
    __syncwarp();

    const int page = nidx[qid];
    const size_t base = (((size_t)(b * H_ + h)) * NP2 + page) * (NS_ * DH_);
    const float* Kp = g_K + base;
    const float* Vp = g_V + base;

    // score for s = lane
    const float4* K4 = (const float4*)(Kp + lane * DH_);
    const float4* Q4 = (const float4*)sq[w];
    float sc = 0.f;
#pragma unroll
    for (int i = 0; i < 16; i++) {
        const float4 kk = K4[i];
        const float4 qq = Q4[i];
        sc = fmaf(kk.x, qq.x, fmaf(kk.y, qq.y, fmaf(kk.z, qq.z, fmaf(kk.w, qq.w, sc))));
    }
    sc *= 0.125f;   // 1/sqrt(64)

    // softmax over the 32 lanes
    float mx = sc;
#pragma unroll
    for (int o = 16; o; o >>= 1) mx = fmaxf(mx, __shfl_xor_sync(0xffffffffu, mx, o));
    const float e = __expf(sc - mx);
    float sum = e;
#pragma unroll
    for (int o = 16; o; o >>= 1) sum += __shfl_xor_sync(0xffffffffu, sum, o);
    const float pr = e / sum;

    // out[d] = sum_s pr[s] * V[s][d]; lane handles d = lane and lane+32
    float o0 = 0.f, o1 = 0.f;
#pragma unroll
    for (int s = 0; s < 32; s++) {
        const float ps = __shfl_sync(0xffffffffu, pr, s);
        o0 = fmaf(ps, Vp[s * DH_ + lane],      o0);
        o1 = fmaf(ps, Vp[s * DH_ + lane + 32], o1);
    }

    float* op = outA + ((size_t)b * NV_ + nv) * C_ + h * DH_;
    op[lane]      = o0;
    op[lane + 32] = o1;
}

// ---------------------------------------------------------------------------
// Launch
// ---------------------------------------------------------------------------
extern "C" void kernel_launch(void* const* d_in, const int* in_sizes, int n_in,
                              void* d_out, int out_size)
{
    const float* q_feat     = (const float*)d_in[0];
    const float* group_feat = (const float*)d_in[1];
    const float* k_pos      = (const float*)d_in[2];
    const int*   nidx       = (const int*)  d_in[3];
    const float* Wq = (const float*)d_in[4];  const float* bq = (const float*)d_in[5];
    const float* Wk = (const float*)d_in[6];  const float* bk = (const float*)d_in[7];
    const float* Wv = (const float*)d_in[8];  const float* bv = (const float*)d_in[9];
    const float* Wo = (const float*)d_in[10]; const float* bo = (const float*)d_in[11];
    float* out = (float*)d_out;

    float *gK, *gV, *gQ, *gA;
    cudaGetSymbolAddress((void**)&gK, g_K);
    cudaGetSymbolAddress((void**)&gV, g_V);
    cudaGetSymbolAddress((void**)&gQ, g_Q);
    cudaGetSymbolAddress((void**)&gA, g_Ao);

    // K projection: (gf + kp) @ Wk^T + bk  -> g_K [B,H,NP,NS,DH]
    kv_proj_kernel<<<dim3(MKV / 128, C_ / 128, B_), 256>>>(
        group_feat, k_pos, Wk, bk, gK, 1);
    // V projection: gf @ Wv^T + bv -> g_V
    kv_proj_kernel<<<dim3(MKV / 128, C_ / 128, B_), 256>>>(
        group_feat, k_pos, Wv, bv, gV, 0);
    // Q projection: q_feat @ Wq^T + bq -> g_Q [B,H,NV,DH]
    rm_gemm_kernel<<<dim3(MQ / 128, C_ / 128, 1), 256>>>(
        q_feat, Wq, bq, gQ, 0);
    // Attention -> g_Ao [B,NV,C]
    attn_kernel<<<(B_ * H_ * NV_) / 8, 256>>>(nidx, gA);
    // Output projection: g_Ao @ Wo^T + bo -> d_out
    rm_gemm_kernel<<<dim3(MQ / 128, C_ / 128, 1), 256>>>(
        gA, Wo, bo, out, 1);
}

// round 2
// speedup vs baseline: 1.1503x; 1.1503x over previous
#include <cuda_runtime.h>
#include <cuda_bf16.h>
#include <cstdint>

// ---------------------------------------------------------------------------
// B=2, NV=8192, C=256, NP=2048, NS=32, H=4, DH=64
// ---------------------------------------------------------------------------
namespace {
constexpr int B_  = 2;
constexpr int NV_ = 8192;
constexpr int C_  = 256;
constexpr int NP2 = 2048;
constexpr int NS_ = 32;
constexpr int H_  = 4;
constexpr int DH_ = 64;
constexpr int MKV = NP2 * NS_;     // 65536 rows per batch (K/V projection)
constexpr int MQ  = B_ * NV_;      // 16384 rows (Q / O projection)
constexpr int AP  = 136;           // sA pitch in bf16 (272B, conflict-free ldmatrix)
constexpr int BP  = 24;            // sB pitch in bf16 (48B, conflict-free LDS)
}

__device__ float g_K[(size_t)B_ * H_ * NP2 * NS_ * DH_];   // [B,H,NP,NS,DH]
__device__ float g_V[(size_t)B_ * H_ * NP2 * NS_ * DH_];
__device__ float g_Q[(size_t)B_ * H_ * NV_ * DH_];         // [B,H,NV,DH]
__device__ float g_Ao[(size_t)B_ * NV_ * C_];              // [B,NV,C]

// ---------------------------------------------------------------------------
// MMA helpers
// ---------------------------------------------------------------------------
__device__ __forceinline__ uint32_t smem_addr(const void* p) {
    return (uint32_t)__cvta_generic_to_shared(p);
}

__device__ __forceinline__ void ldsm4t(uint32_t r[4], uint32_t a) {
    asm volatile("ldmatrix.sync.aligned.m8n8.x4.trans.shared.b16 {%0,%1,%2,%3}, [%4];\n"
                 : "=r"(r[0]), "=r"(r[1]), "=r"(r[2]), "=r"(r[3]) : "r"(a));
}

__device__ __forceinline__ void mma_bf16(float c[4], const uint32_t a[4], const uint32_t b[2]) {
    asm volatile(
        "mma.sync.aligned.m16n8k16.row.col.f32.bf16.bf16.f32 "
        "{%0,%1,%2,%3}, {%4,%5,%6,%7}, {%8,%9}, {%0,%1,%2,%3};\n"
        : "+f"(c[0]), "+f"(c[1]), "+f"(c[2]), "+f"(c[3])
        : "r"(a[0]), "r"(a[1]), "r"(a[2]), "r"(a[3]), "r"(b[0]), "r"(b[1]));
}

// split fp32 pair into bf16 hi / lo planes (hi+lo == x to ~2^-16 rel)
__device__ __forceinline__ void split_pair(float x, float y,
                                           __nv_bfloat162& hi, __nv_bfloat162& lo) {
    __nv_bfloat16 hx = __float2bfloat16(x);
    __nv_bfloat16 hy = __float2bfloat16(y);
    hi.x = hx; hi.y = hy;
    lo.x = __float2bfloat16(x - __bfloat162float(hx));
    lo.y = __float2bfloat16(y - __bfloat162float(hy));
}

// ---------------------------------------------------------------------------
// GEMM 1: K/V projection (tensor core, bf16x3 split).
// A source K-major: A[b][c][m], m = p*NS+s.  out[m,n] = sum_c A[c,m]*W[n,c]+bias
// Epilogue scatters to [B,H,NP,NS,DH].
// Tile 128x128x16, 8 warps (2m x 4n), warp tile 64x32, mma m16n8k16.
// ---------------------------------------------------------------------------
__global__ void __launch_bounds__(256, 1)
kv_proj_mma(const float* __restrict__ gf, const float* __restrict__ kp,
            const float* __restrict__ W, const float* __restrict__ bias,
            float* __restrict__ out, int addKp)
{
    __shared__ __align__(16) __nv_bfloat16 sA[2][2][16][AP];   // [buf][term][k][m]
    __shared__ __align__(16) __nv_bfloat16 sB[2][2][128][BP];  // [buf][term][n][k]

    const int b    = blockIdx.z;
    const int m0   = blockIdx.x * 128;
    const int n0   = blockIdx.y * 128;
    const int tid  = threadIdx.x;
    const int lane = tid & 31;
    const int wid  = tid >> 5;
    const int wm   = (wid & 1) * 64;
    const int wn   = (wid >> 1) * 32;

    const float* A1 = gf + (size_t)b * C_ * MKV;
    const float* A2 = kp + (size_t)b * C_ * MKV;

    // loader mapping
    const int lk = tid >> 5;            // A k-row (and +8)
    const int lm = lane << 2;           // A m-col (4 floats)
    const int bn = tid >> 1;            // B n-row
    const int bk = (tid & 1) << 3;      // B k-col (8 floats)

    // ldmatrix.trans lane addressing: matrix j = lane>>3
    const int jj  = lane >> 3;
    const int akk = ((jj & 2) ? 8 : 0) + (lane & 7);
    const int amm = (jj & 1) ? 8 : 0;
    const int fn  = lane >> 2;          // B frag: n within 8
    const int fc  = (lane & 3) * 2;     // B frag: k pair

    float acc[4][4][4];
#pragma unroll
    for (int i = 0; i < 4; i++)
#pragma unroll
        for (int j = 0; j < 4; j++)
#pragma unroll
            for (int r = 0; r < 4; r++) acc[i][j][r] = 0.f;

    auto ldg_chunk = [&](int kc, float4& x0, float4& x1, float4& y0, float4& y1) {
        const int k0 = kc * 16;
        x0 = *(const float4*)&A1[(size_t)(k0 + lk) * MKV + m0 + lm];
        x1 = *(const float4*)&A1[(size_t)(k0 + lk + 8) * MKV + m0 + lm];
        if (addKp) {
            float4 p0 = *(const float4*)&A2[(size_t)(k0 + lk) * MKV + m0 + lm];
            float4 p1 = *(const float4*)&A2[(size_t)(k0 + lk + 8) * MKV + m0 + lm];
            x0.x += p0.x; x0.y += p0.y; x0.z += p0.z; x0.w += p0.w;
            x1.x += p1.x; x1.y += p1.y; x1.z += p1.z; x1.w += p1.w;
        }
        y0 = *(const float4*)&W[(size_t)(n0 + bn) * C_ + k0 + bk];
        y1 = *(const float4*)&W[(size_t)(n0 + bn) * C_ + k0 + bk + 4];
    };

    auto st_chunk = [&](int buf, const float4& x0, const float4& x1,
                        const float4& y0, const float4& y1) {
        __nv_bfloat162 h, l;
        split_pair(x0.x, x0.y, h, l);
        *(__nv_bfloat162*)&sA[buf][0][lk][lm]         = h;
        *(__nv_bfloat162*)&sA[buf][1][lk][lm]         = l;
        split_pair(x0.z, x0.w, h, l);
        *(__nv_bfloat162*)&sA[buf][0][lk][lm + 2]     = h;
        *(__nv_bfloat162*)&sA[buf][1][lk][lm + 2]     = l;
        split_pair(x1.x, x1.y, h, l);
        *(__nv_bfloat162*)&sA[buf][0][lk + 8][lm]     = h;
        *(__nv_bfloat162*)&sA[buf][1][lk + 8][lm]     = l;
        split_pair(x1.z, x1.w, h, l);
        *(__nv_bfloat162*)&sA[buf][0][lk + 8][lm + 2] = h;
        *(__nv_bfloat162*)&sA[buf][1][lk + 8][lm + 2] = l;

        split_pair(y0.x, y0.y, h, l);
        *(__nv_bfloat162*)&sB[buf][0][bn][bk]     = h;
        *(__nv_bfloat162*)&sB[buf][1][bn][bk]     = l;
        split_pair(y0.z, y0.w, h, l);
        *(__nv_bfloat162*)&sB[buf][0][bn][bk + 2] = h;
        *(__nv_bfloat162*)&sB[buf][1][bn][bk + 2] = l;
        split_pair(y1.x, y1.y, h, l);
        *(__nv_bfloat162*)&sB[buf][0][bn][bk + 4] = h;
        *(__nv_bfloat162*)&sB[buf][1][bn][bk + 4] = l;
        split_pair(y1.z, y1.w, h, l);
        *(__nv_bfloat162*)&sB[buf][0][bn][bk + 6] = h;
        *(__nv_bfloat162*)&sB[buf][1][bn][bk + 6] = l;
    };

    auto compute = [&](int buf) {
        uint32_t Ah[4][4], Al[4][4], Bh[4][2], Bl[4][2];
#pragma unroll
        for (int mf = 0; mf < 4; mf++) {
            const int mc = wm + mf * 16 + amm;
            ldsm4t(Ah[mf], smem_addr(&sA[buf][0][akk][mc]));
            ldsm4t(Al[mf], smem_addr(&sA[buf][1][akk][mc]));
        }
#pragma unroll
        for (int nf = 0; nf < 4; nf++) {
            const int n = wn + nf * 8 + fn;
            Bh[nf][0] = *(const uint32_t*)&sB[buf][0][n][fc];
            Bh[nf][1] = *(const uint32_t*)&sB[buf][0][n][fc + 8];
            Bl[nf][0] = *(const uint32_t*)&sB[buf][1][n][fc];
            Bl[nf][1] = *(const uint32_t*)&sB[buf][1][n][fc + 8];
        }
#pragma unroll
        for (int mf = 0; mf < 4; mf++)
#pragma unroll
            for (int nf = 0; nf < 4; nf++) {
                mma_bf16(acc[mf][nf], Ah[mf], Bh[nf]);
                mma_bf16(acc[mf][nf], Ah[mf], Bl[nf]);
                mma_bf16(acc[mf][nf], Al[mf], Bh[nf]);
            }
    };

    float4 x0, x1, y0, y1;
    ldg_chunk(0, x0, x1, y0, y1);
    st_chunk(0, x0, x1, y0, y1);
    __syncthreads();

    for (int kc = 0; kc < 16; kc++) {
        const int buf = kc & 1;
        if (kc < 15) ldg_chunk(kc + 1, x0, x1, y0, y1);
        compute(buf);
        if (kc < 15) {
            st_chunk(buf ^ 1, x0, x1, y0, y1);
            __syncthreads();
        }
    }

    // epilogue: bias + scatter to [B,H,NP,NS,DH]
#pragma unroll
    for (int mf = 0; mf < 4; mf++)
#pragma unroll
        for (int nf = 0; nf < 4; nf++) {
            const int ncol = n0 + wn + nf * 8 + fc;
            const int hh = ncol >> 6;
            const int d  = ncol & 63;
            const float bx = bias[ncol];
            const float by = bias[ncol + 1];
#pragma unroll
            for (int half = 0; half < 2; half++) {
                const int mrow = m0 + wm + mf * 16 + (lane >> 2) + half * 8;
                const int p = mrow >> 5;
                const int s = mrow & 31;
                float2 o;
                o.x = acc[mf][nf][half * 2]     + bx;
                o.y = acc[mf][nf][half * 2 + 1] + by;
                *(float2*)&out[((((size_t)b * H_ + hh) * NP2 + p) * NS_ + s) * DH_ + d] = o;
            }
        }
}

// ---------------------------------------------------------------------------
// GEMM 2: row-major A [M][256] @ W^T + bias (tensor core, bf16x3 split).
// mode 0: Q projection -> [B,H,NV,DH];  mode 1: O projection -> [M][256]
// ---------------------------------------------------------------------------
__global__ void __launch_bounds__(256, 1)
rm_gemm_mma(const float* __restrict__ A,
            const float* __restrict__ W, const float* __restrict__ bias,
            float* __restrict__ out, int mode)
{
    __shared__ __align__(16) __nv_bfloat16 sA[2][2][16][AP];
    __shared__ __align__(16) __nv_bfloat16 sB[2][2][128][BP];

    const int m0   = blockIdx.x * 128;
    const int n0   = blockIdx.y * 128;
    const int tid  = threadIdx.x;
    const int lane = tid & 31;
    const int wid  = tid >> 5;
    const int wm   = (wid & 1) * 64;
    const int wn   = (wid >> 1) * 32;

    const int am = tid >> 1;            // A m-row
    const int ak = (tid & 1) << 3;      // A k-col (8 floats)
    const int bn = tid >> 1;
    const int bk = (tid & 1) << 3;

    const int jj  = lane >> 3;
    const int akk = ((jj & 2) ? 8 : 0) + (lane & 7);
    const int amm = (jj & 1) ? 8 : 0;
    const int fn  = lane >> 2;
    const int fc  = (lane & 3) * 2;

    float acc[4][4][4];
#pragma unroll
    for (int i = 0; i < 4; i++)
#pragma unroll
        for (int j = 0; j < 4; j++)
#pragma unroll
            for (int r = 0; r < 4; r++) acc[i][j][r] = 0.f;

    auto ldg_chunk = [&](int kc, float4& x0, float4& x1, float4& y0, float4& y1) {
        const int k0 = kc * 16;
        x0 = *(const float4*)&A[(size_t)(m0 + am) * C_ + k0 + ak];
        x1 = *(const float4*)&A[(size_t)(m0 + am) * C_ + k0 + ak + 4];
        y0 = *(const float4*)&W[(size_t)(n0 + bn) * C_ + k0 + bk];
        y1 = *(const float4*)&W[(size_t)(n0 + bn) * C_ + k0 + bk + 4];
    };

    auto st_chunk = [&](int buf, const float4& x0, const float4& x1,
                        const float4& y0, const float4& y1) {
        // A transposed into [k][m]: 8 scalar bf16 stores per plane
        const float v[8] = {x0.x, x0.y, x0.z, x0.w, x1.x, x1.y, x1.z, x1.w};
#pragma unroll
        for (int i = 0; i < 8; i++) {
            __nv_bfloat16 h = __float2bfloat16(v[i]);
            sA[buf][0][ak + i][am] = h;
            sA[buf][1][ak + i][am] = __float2bfloat16(v[i] - __bfloat162float(h));
        }
        __nv_bfloat162 h, l;
        split_pair(y0.x, y0.y, h, l);
        *(__nv_bfloat162*)&sB[buf][0][bn][bk]     = h;
        *(__nv_bfloat162*)&sB[buf][1][bn][bk]     = l;
        split_pair(y0.z, y0.w, h, l);
        *(__nv_bfloat162*)&sB[buf][0][bn][bk + 2] = h;
        *(__nv_bfloat162*)&sB[buf][1][bn][bk + 2] = l;
        split_pair(y1.x, y1.y, h, l);
        *(__nv_bfloat162*)&sB[buf][0][bn][bk + 4] = h;
        *(__nv_bfloat162*)&sB[buf][1][bn][bk + 4] = l;
        split_pair(y1.z, y1.w, h, l);
        *(__nv_bfloat162*)&sB[buf][0][bn][bk + 6] = h;
        *(__nv_bfloat162*)&sB[buf][1][bn][bk + 6] = l;
    };

    auto compute = [&](int buf) {
        uint32_t Ah[4][4], Al[4][4], Bh[4][2], Bl[4][2];
#pragma unroll
        for (int mf = 0; mf < 4; mf++) {
            const int mc = wm + mf * 16 + amm;
            ldsm4t(Ah[mf], smem_addr(&sA[buf][0][akk][mc]));
            ldsm4t(Al[mf], smem_addr(&sA[buf][1][akk][mc]));
        }
#pragma unroll
        for (int nf = 0; nf < 4; nf++) {
            const int n = wn + nf * 8 + fn;
            Bh[nf][0] = *(const uint32_t*)&sB[buf][0][n][fc];
            Bh[nf][1] = *(const uint32_t*)&sB[buf][0][n][fc + 8];
            Bl[nf][0] = *(const uint32_t*)&sB[buf][1][n][fc];
            Bl[nf][1] = *(const uint32_t*)&sB[buf][1][n][fc + 8];
        }
#pragma unroll
        for (int mf = 0; mf < 4; mf++)
#pragma unroll
            for (int nf = 0; nf < 4; nf++) {
                mma_bf16(acc[mf][nf], Ah[mf], Bh[nf]);
                mma_bf16(acc[mf][nf], Ah[mf], Bl[nf]);
                mma_bf16(acc[mf][nf], Al[mf], Bh[nf]);
            }
    };

    float4 x0, x1, y0, y1;
    ldg_chunk(0, x0, x1, y0, y1);
    st_chunk(0, x0, x1, y0, y1);
    __syncthreads();

    for (int kc = 0; kc < 16; kc++) {
        const int buf = kc & 1;
        if (kc < 15) ldg_chunk(kc + 1, x0, x1, y0, y1);
        compute(buf);
        if (kc < 15) {
            st_chunk(buf ^ 1, x0, x1, y0, y1);
            __syncthreads();
        }
    }

#pragma unroll
    for (int mf = 0; mf < 4; mf++)
#pragma unroll
        for (int nf = 0; nf < 4; nf++) {
            const int ncol = n0 + wn + nf * 8 + fc;
            const float bx = bias[ncol];
            const float by = bias[ncol + 1];
#pragma unroll
            for (int half = 0; half < 2; half++) {
                const int mrow = m0 + wm + mf * 16 + (lane >> 2) + half * 8;
                float2 o;
                o.x = acc[mf][nf][half * 2]     + bx;
                o.y = acc[mf][nf][half * 2 + 1] + by;
                if (mode == 0) {
                    const int bb = mrow >> 13;
                    const int nv = mrow & (NV_ - 1);
                    const int hh = ncol >> 6;
                    const int d  = ncol & 63;
                    *(float2*)&g_Q[(((size_t)(bb * H_ + hh)) * NV_ + nv) * DH_ + d] = o;
                } else {
                    *(float2*)&out[(size_t)mrow * C_ + ncol] = o;
                }
            }
        }
}

// ---------------------------------------------------------------------------
// Attention: one warp per query. Vectorized K/V loads (wavefront-optimal).
// ---------------------------------------------------------------------------
__global__ void __launch_bounds__(256)
attn_kernel(const int* __restrict__ nidx, float* __restrict__ outA)
{
    __shared__ __align__(16) float sq[8][64];
    const int w    = threadIdx.x >> 5;
    const int lane = threadIdx.x & 31;
    const int qid  = blockIdx.x * 8 + w;

    const int b  = qid >> 15;
    const int h  = (qid >> 13) & 3;
    const int nv = qid & (NV_ - 1);

    if (lane < 16)
        *(float4*)&sq[w][lane * 4] = *(const float4*)&g_Q[(size_t)qid * DH_ + lane * 4];
    __syncwarp();

    const int page = nidx[qid];
    const size_t base = (((size_t)(b * H_ + h)) * NP2 + page) * (NS_ * DH_);
    const float* Kp = g_K + base;
    const float* Vp = g_V + base;

    // score for s = lane
    const float4* K4 = (const float4*)(Kp + lane * DH_);
    const float4* Q4 = (const float4*)sq[w];
    float sc = 0.f;
#pragma unroll
    for (int i = 0; i < 16; i++) {
        const float4 kk = K4[i];
        const float4 qq = Q4[i];
        sc = fmaf(kk.x, qq.x, fmaf(kk.y, qq.y, fmaf(kk.z, qq.z, fmaf(kk.w, qq.w, sc))));
    }
    sc *= 0.125f;

    float mx = sc;
#pragma unroll
    for (int o = 16; o; o >>= 1) mx = fmaxf(mx, __shfl_xor_sync(0xffffffffu, mx, o));
    const float e = __expf(sc - mx);
    float sum = e;
#pragma unroll
    for (int o = 16; o; o >>= 1) sum += __shfl_xor_sync(0xffffffffu, sum, o);
    const float pr = e / sum;

    // out[d] = sum_s pr[s]*V[s][d].  Lane owns d-quad (lane&15)*4, s-half lane>>4.
    const int d0 = (lane & 15) * 4;
    const int sb = (lane >> 4) * 16;
    const float* Vl = Vp + (size_t)sb * DH_ + d0;
    float4 o = {0.f, 0.f, 0.f, 0.f};
#pragma unroll
    for (int i = 0; i < 16; i++) {
        const float ps = __shfl_sync(0xffffffffu, pr, sb + i);
        const float4 v = *(const float4*)&Vl[i * DH_];
        o.x = fmaf(ps, v.x, o.x);
        o.y = fmaf(ps, v.y, o.y);
        o.z = fmaf(ps, v.z, o.z);
        o.w = fmaf(ps, v.w, o.w);
    }
    o.x += __shfl_xor_sync(0xffffffffu, o.x, 16);
    o.y += __shfl_xor_sync(0xffffffffu, o.y, 16);
    o.z += __shfl_xor_sync(0xffffffffu, o.z, 16);
    o.w += __shfl_xor_sync(0xffffffffu, o.w, 16);

    if (lane < 16) {
        float* op = outA + ((size_t)b * NV_ + nv) * C_ + h * DH_;
        *(float4*)&op[d0] = o;
    }
}

// ---------------------------------------------------------------------------
// Launch
// ---------------------------------------------------------------------------
extern "C" void kernel_launch(void* const* d_in, const int* in_sizes, int n_in,
                              void* d_out, int out_size)
{
    const float* q_feat     = (const float*)d_in[0];
    const float* group_feat = (const float*)d_in[1];
    const float* k_pos      = (const float*)d_in[2];
    const int*   nidx       = (const int*)  d_in[3];
    const float* Wq = (const float*)d_in[4];  const float* bq = (const float*)d_in[5];
    const float* Wk = (const float*)d_in[6];  const float* bk = (const float*)d_in[7];
    const float* Wv = (const float*)d_in[8];  const float* bv = (const float*)d_in[9];
    const float* Wo = (const float*)d_in[10]; const float* bo = (const float*)d_in[11];
    float* out = (float*)d_out;

    float *gK, *gV, *gQ, *gA;
    cudaGetSymbolAddress((void**)&gK, g_K);
    cudaGetSymbolAddress((void**)&gV, g_V);
    cudaGetSymbolAddress((void**)&gQ, g_Q);
    cudaGetSymbolAddress((void**)&gA, g_Ao);

    // K projection: (gf + kp) @ Wk^T + bk -> g_K [B,H,NP,NS,DH]
    kv_proj_mma<<<dim3(MKV / 128, C_ / 128, B_), 256>>>(group_feat, k_pos, Wk, bk, gK, 1);
    // V projection: gf @ Wv^T + bv -> g_V
    kv_proj_mma<<<dim3(MKV / 128, C_ / 128, B_), 256>>>(group_feat, k_pos, Wv, bv, gV, 0);
    // Q projection -> g_Q [B,H,NV,DH]  (mode 0 writes g_Q internally)
    rm_gemm_mma<<<dim3(MQ / 128, C_ / 128, 1), 256>>>(q_feat, Wq, bq, gQ, 0);
    // Attention -> g_Ao [B,NV,C]
    attn_kernel<<<(B_ * H_ * NV_) / 8, 256>>>(nidx, gA);
    // Output projection -> d_out
    rm_gemm_mma<<<dim3(MQ / 128, C_ / 128, 1), 256>>>(gA, Wo, bo, out, 1);
}

// round 3
// speedup vs baseline: 1.8461x; 1.6049x over previous
#include <cuda_runtime.h>
#include <cuda_bf16.h>
#include <cstdint>

// ---------------------------------------------------------------------------
// B=2, NV=8192, C=256, NP=2048, NS=32, H=4, DH=64
// ---------------------------------------------------------------------------
namespace {
constexpr int B_  = 2;
constexpr int NV_ = 8192;
constexpr int C_  = 256;
constexpr int NP2 = 2048;
constexpr int NS_ = 32;
constexpr int H_  = 4;
constexpr int DH_ = 64;
constexpr int MQ  = B_ * NV_;          // 16384
constexpr int NQT = B_ * H_ * NV_;     // 65536 queries
constexpr int NBIN = B_ * NP2;         // 4096 bins
constexpr int AP  = 136;               // sA pitch (bf16)
constexpr int BP  = 24;                // sB pitch (bf16)
constexpr int ROWP = 33;               // smem page row pitch (floats)
}

// scratch
__device__ float g_Q  [(size_t)NQT * DH_];        // [B,H,NV,64]   16 MB
__device__ float g_Qt [(size_t)NQT * C_];         // [B,H,NV,256]  64 MB
__device__ float g_Hat[(size_t)MQ * H_ * C_];     // [B,NV,H,256]  64 MB
__device__ float g_WkT[C_ * C_];                  // Wk^T
__device__ float g_WvT[C_ * C_];                  // Wv^T
__device__ float g_Mcat[(size_t)C_ * (H_ * C_)];  // [256][1024]
__device__ float g_btld[C_];
__device__ int   g_cnt[NBIN];
__device__ int   g_off[NBIN + 1];
__device__ int   g_cur[NBIN];
__device__ int   g_ent[NQT];

// ---------------------------------------------------------------------------
// MMA helpers (bf16x3 split emulating fp32)
// ---------------------------------------------------------------------------
__device__ __forceinline__ uint32_t smem_u32(const void* p) {
    return (uint32_t)__cvta_generic_to_shared(p);
}
__device__ __forceinline__ void ldsm4t(uint32_t r[4], uint32_t a) {
    asm volatile("ldmatrix.sync.aligned.m8n8.x4.trans.shared.b16 {%0,%1,%2,%3}, [%4];\n"
                 : "=r"(r[0]), "=r"(r[1]), "=r"(r[2]), "=r"(r[3]) : "r"(a));
}
__device__ __forceinline__ void mma_bf16(float c[4], const uint32_t a[4], const uint32_t b[2]) {
    asm volatile(
        "mma.sync.aligned.m16n8k16.row.col.f32.bf16.bf16.f32 "
        "{%0,%1,%2,%3}, {%4,%5,%6,%7}, {%8,%9}, {%0,%1,%2,%3};\n"
        : "+f"(c[0]), "+f"(c[1]), "+f"(c[2]), "+f"(c[3])
        : "r"(a[0]), "r"(a[1]), "r"(a[2]), "r"(a[3]), "r"(b[0]), "r"(b[1]));
}
__device__ __forceinline__ void split_pair(float x, float y,
                                           __nv_bfloat162& hi, __nv_bfloat162& lo) {
    __nv_bfloat16 hx = __float2bfloat16(x);
    __nv_bfloat16 hy = __float2bfloat16(y);
    hi.x = hx; hi.y = hy;
    lo.x = __float2bfloat16(x - __bfloat162float(hx));
    lo.y = __float2bfloat16(y - __bfloat162float(hy));
}

// ---------------------------------------------------------------------------
// Generic GEMM: out[m,n] = sum_k A[m, k] * W[n, k] (+bias[n])
// A row-major (lda), W row-major [N][ldb]. Tile 128x128x16, 8 warps.
// mode 0: permute write for Q projection -> out is g_Q-layout [B,H,NV,64]
// mode 1: plain out[mrow*ldo + ncol]
// headsel: W += ((m0>>13)&3)*64   (per-head B slice for Qt GEMM)
// ---------------------------------------------------------------------------
__global__ void __launch_bounds__(256, 1)
gemm_bf3(const float* __restrict__ A, int lda,
         const float* __restrict__ W, int ldb, int K,
         const float* __restrict__ bias,
         float* __restrict__ out, int ldo, int mode, int headsel)
{
    __shared__ __align__(16) __nv_bfloat16 sA[2][2][16][AP];
    __shared__ __align__(16) __nv_bfloat16 sB[2][2][128][BP];

    const int m0   = blockIdx.x * 128;
    const int n0   = blockIdx.y * 128;
    const int tid  = threadIdx.x;
    const int lane = tid & 31;
    const int wid  = tid >> 5;
    const int wm   = (wid & 1) * 64;
    const int wn   = (wid >> 1) * 32;

    const float* Wp = W + (headsel ? (size_t)((m0 >> 13) & 3) * 64 : 0);

    const int am = tid >> 1;
    const int ak = (tid & 1) << 3;
    const int bn = tid >> 1;
    const int bk = (tid & 1) << 3;

    const int jj  = lane >> 3;
    const int akk = ((jj & 2) ? 8 : 0) + (lane & 7);
    const int amm = (jj & 1) ? 8 : 0;
    const int fn  = lane >> 2;
    const int fc  = (lane & 3) * 2;

    float acc[4][4][4];
#pragma unroll
    for (int i = 0; i < 4; i++)
#pragma unroll
        for (int j = 0; j < 4; j++)
#pragma unroll
            for (int r = 0; r < 4; r++) acc[i][j][r] = 0.f;

    auto ldg_chunk = [&](int kc, float4& x0, float4& x1, float4& y0, float4& y1) {
        const int k0 = kc * 16;
        x0 = *(const float4*)&A[(size_t)(m0 + am) * lda + k0 + ak];
        x1 = *(const float4*)&A[(size_t)(m0 + am) * lda + k0 + ak + 4];
        y0 = *(const float4*)&Wp[(size_t)(n0 + bn) * ldb + k0 + bk];
        y1 = *(const float4*)&Wp[(size_t)(n0 + bn) * ldb + k0 + bk + 4];
    };

    auto st_chunk = [&](int buf, const float4& x0, const float4& x1,
                        const float4& y0, const float4& y1) {
        const float v[8] = {x0.x, x0.y, x0.z, x0.w, x1.x, x1.y, x1.z, x1.w};
#pragma unroll
        for (int i = 0; i < 8; i++) {
            __nv_bfloat16 h = __float2bfloat16(v[i]);
            sA[buf][0][ak + i][am] = h;
            sA[buf][1][ak + i][am] = __float2bfloat16(v[i] - __bfloat162float(h));
        }
        __nv_bfloat162 h, l;
        split_pair(y0.x, y0.y, h, l);
        *(__nv_bfloat162*)&sB[buf][0][bn][bk]     = h;
        *(__nv_bfloat162*)&sB[buf][1][bn][bk]     = l;
        split_pair(y0.z, y0.w, h, l);
        *(__nv_bfloat162*)&sB[buf][0][bn][bk + 2] = h;
        *(__nv_bfloat162*)&sB[buf][1][bn][bk + 2] = l;
        split_pair(y1.x, y1.y, h, l);
        *(__nv_bfloat162*)&sB[buf][0][bn][bk + 4] = h;
        *(__nv_bfloat162*)&sB[buf][1][bn][bk + 4] = l;
        split_pair(y1.z, y1.w, h, l);
        *(__nv_bfloat162*)&sB[buf][0][bn][bk + 6] = h;
        *(__nv_bfloat162*)&sB[buf][1][bn][bk + 6] = l;
    };

    auto compute = [&](int buf) {
        uint32_t Ah[4][4], Al[4][4], Bh[4][2], Bl[4][2];
#pragma unroll
        for (int mf = 0; mf < 4; mf++) {
            const int mc = wm + mf * 16 + amm;
            ldsm4t(Ah[mf], smem_u32(&sA[buf][0][akk][mc]));
            ldsm4t(Al[mf], smem_u32(&sA[buf][1][akk][mc]));
        }
#pragma unroll
        for (int nf = 0; nf < 4; nf++) {
            const int n = wn + nf * 8 + fn;
            Bh[nf][0] = *(const uint32_t*)&sB[buf][0][n][fc];
            Bh[nf][1] = *(const uint32_t*)&sB[buf][0][n][fc + 8];
            Bl[nf][0] = *(const uint32_t*)&sB[buf][1][n][fc];
            Bl[nf][1] = *(const uint32_t*)&sB[buf][1][n][fc + 8];
        }
#pragma unroll
        for (int mf = 0; mf < 4; mf++)
#pragma unroll
            for (int nf = 0; nf < 4; nf++) {
                mma_bf16(acc[mf][nf], Ah[mf], Bh[nf]);
                mma_bf16(acc[mf][nf], Ah[mf], Bl[nf]);
                mma_bf16(acc[mf][nf], Al[mf], Bh[nf]);
            }
    };

    const int NKC = K / 16;
    float4 x0, x1, y0, y1;
    ldg_chunk(0, x0, x1, y0, y1);
    st_chunk(0, x0, x1, y0, y1);
    __syncthreads();

    for (int kc = 0; kc < NKC; kc++) {
        const int buf = kc & 1;
        if (kc + 1 < NKC) ldg_chunk(kc + 1, x0, x1, y0, y1);
        compute(buf);
        if (kc + 1 < NKC) {
            st_chunk(buf ^ 1, x0, x1, y0, y1);
            __syncthreads();
        }
    }

#pragma unroll
    for (int mf = 0; mf < 4; mf++)
#pragma unroll
        for (int nf = 0; nf < 4; nf++) {
            const int ncol = n0 + wn + nf * 8 + fc;
            const float bx = bias ? bias[ncol]     : 0.f;
            const float by = bias ? bias[ncol + 1] : 0.f;
#pragma unroll
            for (int half = 0; half < 2; half++) {
                const int mrow = m0 + wm + mf * 16 + (lane >> 2) + half * 8;
                float2 o;
                o.x = acc[mf][nf][half * 2]     + bx;
                o.y = acc[mf][nf][half * 2 + 1] + by;
                if (mode == 0) {
                    const int bb = mrow >> 13;
                    const int nv = mrow & (NV_ - 1);
                    const int hh = ncol >> 6;
                    const int d  = ncol & 63;
                    *(float2*)&out[(((size_t)(bb * H_ + hh)) * NV_ + nv) * DH_ + d] = o;
                } else {
                    *(float2*)&out[(size_t)mrow * ldo + ncol] = o;
                }
            }
        }
}

// ---------------------------------------------------------------------------
// Precompute kernels
// ---------------------------------------------------------------------------
__global__ void transpose_kernel(const float* __restrict__ Wk,
                                 const float* __restrict__ Wv) {
    const int r = blockIdx.x;          // 256
    const int c = threadIdx.x;         // 256
    g_WkT[c * C_ + r] = Wk[r * C_ + c];
    g_WvT[c * C_ + r] = Wv[r * C_ + c];
}

// Mcat[i][h*256+c] = sum_d Wo[i][h*64+d] * WvT[c][h*64+d]
__global__ void mcat_kernel(const float* __restrict__ Wo) {
    const int T  = blockIdx.x * 256 + threadIdx.x;   // 256*1024 threads
    const int i  = T >> 10;
    const int hc = T & 1023;
    const int h  = hc >> 8;
    const int c  = hc & 255;
    const float* wo = Wo + (size_t)i * C_ + h * 64;
    const float* wv = g_WvT + (size_t)c * C_ + h * 64;
    float s = 0.f;
#pragma unroll 8
    for (int d = 0; d < 64; d++) s = fmaf(wo[d], wv[d], s);
    g_Mcat[(size_t)i * 1024 + hc] = s;
}

__global__ void btld_kernel(const float* __restrict__ Wo,
                            const float* __restrict__ bv,
                            const float* __restrict__ bo) {
    const int i = threadIdx.x;   // 256
    float s = bo[i];
    for (int j = 0; j < C_; j++) s = fmaf(Wo[(size_t)i * C_ + j], bv[j], s);
    g_btld[i] = s;
}

// ---------------------------------------------------------------------------
// Bucketing: zero / histogram / scan / scatter
// ---------------------------------------------------------------------------
__global__ void zero_cnt_kernel() {
    g_cnt[blockIdx.x * 256 + threadIdx.x] = 0;
}

__global__ void hist_kernel(const int* __restrict__ nidx) {
    const int t = blockIdx.x * 256 + threadIdx.x;   // 65536
    const int b = t >> 15;
    const int page = nidx[t];
    atomicAdd(&g_cnt[(b << 11) | page], 1);
}

__global__ void scan_kernel() {
    __shared__ int tsum[1024];
    const int t = threadIdx.x;
    const int4 v = ((const int4*)g_cnt)[t];
    const int s0 = v.x, s01 = v.x + v.y, s012 = s01 + v.z;
    const int tot = s012 + v.w;
    tsum[t] = tot;
    __syncthreads();
    for (int off = 1; off < 1024; off <<= 1) {
        int x = (t >= off) ? tsum[t - off] : 0;
        __syncthreads();
        tsum[t] += x;
        __syncthreads();
    }
    const int base = tsum[t] - tot;   // exclusive
    g_off[4 * t]     = base;          g_cur[4 * t]     = base;
    g_off[4 * t + 1] = base + s0;     g_cur[4 * t + 1] = base + s0;
    g_off[4 * t + 2] = base + s01;    g_cur[4 * t + 2] = base + s01;
    g_off[4 * t + 3] = base + s012;   g_cur[4 * t + 3] = base + s012;
    if (t == 1023) g_off[NBIN] = tsum[1023];
}

__global__ void scatter_kernel(const int* __restrict__ nidx) {
    const int t = blockIdx.x * 256 + threadIdx.x;   // 65536
    const int b  = t >> 15;
    const int h  = (t >> 13) & 3;
    const int nv = t & (NV_ - 1);
    const int page = nidx[t];
    const int pos = atomicAdd(&g_cur[(b << 11) | page], 1);
    g_ent[pos] = (h << 16) | nv;
}

// ---------------------------------------------------------------------------
// Bucketed attention. One CTA per (b,page). Loads gf page + (gf+kp) page to
// smem (pad-33 rows -> conflict-free for both column and row access), then
// each warp handles one query: scores over C=256, softmax over 32 lanes,
// ghat accumulation -> g_Hat [B,NV,H,256].
// ---------------------------------------------------------------------------
__global__ void __launch_bounds__(256)
attn_pages(const float* __restrict__ gf, const float* __restrict__ kp)
{
    extern __shared__ float sm[];
    float* ssum = sm;                    // [256][33]: gf+kp
    float* sgf  = sm + 256 * ROWP;       // [256][33]: gf

    const int bin  = blockIdx.x;
    const int b    = bin >> 11;
    const int page = bin & (NP2 - 1);
    const int off  = g_off[bin];
    const int cnt  = g_off[bin + 1] - off;
    if (cnt == 0) return;

    const int tid  = threadIdx.x;
    const int lane = tid & 31;
    const int w    = tid >> 5;

    const float* gfb = gf + (size_t)b * C_ * (NP2 * NS_) + page * NS_;
    const float* kpb = kp + (size_t)b * C_ * (NP2 * NS_) + page * NS_;

#pragma unroll
    for (int it = 0; it < 8; it++) {
        const int i = it * 256 + tid;      // 2048 float4 slots
        const int c = i >> 3;
        const int j = (i & 7) * 4;
        const float4 g = *(const float4*)(gfb + (size_t)c * (NP2 * NS_) + j);
        const float4 k = *(const float4*)(kpb + (size_t)c * (NP2 * NS_) + j);
        float* pg = sgf  + c * ROWP + j;
        float* ps = ssum + c * ROWP + j;
        pg[0] = g.x; pg[1] = g.y; pg[2] = g.z; pg[3] = g.w;
        ps[0] = g.x + k.x; ps[1] = g.y + k.y; ps[2] = g.z + k.z; ps[3] = g.w + k.w;
    }
    __syncthreads();

    for (int e = w; e < cnt; e += 8) {
        const int ent = g_ent[off + e];
        const int h   = ent >> 16;
        const int nv  = ent & 0xffff;
        const size_t qrow = ((size_t)(b * H_ + h)) * NV_ + nv;

        // lane holds q-tilde[ lane*8 .. lane*8+7 ]
        const float4 qa = *(const float4*)&g_Qt[qrow * C_ + lane * 8];
        const float4 qb = *(const float4*)&g_Qt[qrow * C_ + lane * 8 + 4];
        const float q[8] = {qa.x, qa.y, qa.z, qa.w, qb.x, qb.y, qb.z, qb.w};

        // score for s = lane
        float sc = 0.f;
#pragma unroll 4
        for (int src = 0; src < 32; src++) {
#pragma unroll
            for (int j = 0; j < 8; j++) {
                const float qc = __shfl_sync(0xffffffffu, q[j], src);
                sc = fmaf(qc, ssum[(src * 8 + j) * ROWP + lane], sc);
            }
        }
        sc *= 0.125f;

        float mx = sc;
#pragma unroll
        for (int o = 16; o; o >>= 1) mx = fmaxf(mx, __shfl_xor_sync(0xffffffffu, mx, o));
        const float ex = __expf(sc - mx);
        float sum = ex;
#pragma unroll
        for (int o = 16; o; o >>= 1) sum += __shfl_xor_sync(0xffffffffu, sum, o);
        const float pr = ex / sum;

        // ghat: lane owns c = lane + 32k
        float acc[8] = {0.f, 0.f, 0.f, 0.f, 0.f, 0.f, 0.f, 0.f};
#pragma unroll 8
        for (int s = 0; s < 32; s++) {
            const float a = __shfl_sync(0xffffffffu, pr, s);
#pragma unroll
            for (int k = 0; k < 8; k++)
                acc[k] = fmaf(a, sgf[(lane + 32 * k) * ROWP + s], acc[k]);
        }

        float* op = g_Hat + (((size_t)(b * NV_ + nv)) * H_ + h) * C_;
#pragma unroll
        for (int k = 0; k < 8; k++) op[lane + 32 * k] = acc[k];
    }
}

// ---------------------------------------------------------------------------
// Launch
// ---------------------------------------------------------------------------
extern "C" void kernel_launch(void* const* d_in, const int* in_sizes, int n_in,
                              void* d_out, int out_size)
{
    const float* q_feat     = (const float*)d_in[0];
    const float* group_feat = (const float*)d_in[1];
    const float* k_pos      = (const float*)d_in[2];
    const int*   nidx       = (const int*)  d_in[3];
    const float* Wq = (const float*)d_in[4];  const float* bq = (const float*)d_in[5];
    const float* Wk = (const float*)d_in[6];
    const float* Wv = (const float*)d_in[8];  const float* bv = (const float*)d_in[9];
    const float* Wo = (const float*)d_in[10]; const float* bo = (const float*)d_in[11];
    float* out = (float*)d_out;

    float *gQ, *gQt, *gHat, *gWkT, *gMcat, *gbtld;
    cudaGetSymbolAddress((void**)&gQ,    g_Q);
    cudaGetSymbolAddress((void**)&gQt,   g_Qt);
    cudaGetSymbolAddress((void**)&gHat,  g_Hat);
    cudaGetSymbolAddress((void**)&gWkT,  g_WkT);
    cudaGetSymbolAddress((void**)&gMcat, g_Mcat);
    cudaGetSymbolAddress((void**)&gbtld, g_btld);

    const int attn_smem = 2 * 256 * ROWP * (int)sizeof(float);   // 67584
    cudaFuncSetAttribute(attn_pages, cudaFuncAttributeMaxDynamicSharedMemorySize,
                         attn_smem);

    // precompute
    transpose_kernel<<<256, 256>>>(Wk, Wv);
    mcat_kernel<<<1024, 256>>>(Wo);
    btld_kernel<<<1, 256>>>(Wo, bv, bo);

    // bucketing
    zero_cnt_kernel<<<NBIN / 256, 256>>>();
    hist_kernel<<<NQT / 256, 256>>>(nidx);
    scan_kernel<<<1, 1024>>>();
    scatter_kernel<<<NQT / 256, 256>>>(nidx);

    // Q projection: q_feat @ Wq^T + bq -> g_Q [B,H,NV,64]
    gemm_bf3<<<dim3(MQ / 128, 2), 256>>>(q_feat, C_, Wq, C_, C_, bq, gQ, 0, 0, 0);
    // Q-tilde: g_Q @ WkT_h -> g_Qt [B,H,NV,256]
    gemm_bf3<<<dim3(NQT / 128, 2), 256>>>(gQ, DH_, gWkT, C_, DH_, nullptr,
                                          gQt, C_, 1, 1);
    // bucketed attention -> g_Hat [B,NV,H,256]
    attn_pages<<<NBIN, 256, attn_smem>>>(group_feat, k_pos);
    // final: g_Hat [16384,1024] @ Mcat^T + btld -> out [B,NV,256]
    gemm_bf3<<<dim3(MQ / 128, 2), 256>>>(gHat, H_ * C_, gMcat, H_ * C_, H_ * C_,
                                         gbtld, out, C_, 1, 0);
}

// round 4
// speedup vs baseline: 2.1648x; 1.1727x over previous
#include <cuda_runtime.h>
#include <cuda_bf16.h>
#include <cstdint>

// ---------------------------------------------------------------------------
// B=2, NV=8192, C=256, NP=2048, NS=32, H=4, DH=64
// ---------------------------------------------------------------------------
namespace {
constexpr int B_   = 2;
constexpr int NV_  = 8192;
constexpr int C_   = 256;
constexpr int NP2  = 2048;
constexpr int NS_  = 32;
constexpr int H_   = 4;
constexpr int DH_  = 64;
constexpr int MQ   = B_ * NV_;          // 16384
constexpr int NQT  = B_ * H_ * NV_;     // 65536 queries
constexpr int NBIN = B_ * NP2;          // 4096 bins
constexpr int SP   = 24;                // smem tile pitch (bf16), 48B rows
constexpr int ROWP = 33;                // attention smem row pitch (floats)
}

// bf16 hi/lo operand planes + fp32 scratch
__device__ __nv_bfloat16 g_qfh[(size_t)MQ * C_],  g_qfl[(size_t)MQ * C_];
__device__ __nv_bfloat16 g_Qh [(size_t)NQT * DH_], g_Ql [(size_t)NQT * DH_];
__device__ float         g_Qt [(size_t)NQT * C_];                    // fp32, 64MB
__device__ __nv_bfloat16 g_Hth[(size_t)MQ * H_ * C_], g_Htl[(size_t)MQ * H_ * C_];
__device__ __nv_bfloat16 g_vh [(size_t)MQ * C_],  g_vl [(size_t)MQ * C_];
__device__ __nv_bfloat16 g_Wqh[C_ * C_], g_Wql[C_ * C_];
__device__ __nv_bfloat16 g_WkTh[C_ * C_], g_WkTl[C_ * C_];
__device__ __nv_bfloat16 g_Wvh[C_ * C_], g_Wvl[C_ * C_];
__device__ __nv_bfloat16 g_Woh[C_ * C_], g_Wol[C_ * C_];
__device__ float g_btld[C_];
__device__ int   g_cnt[NBIN];
__device__ int   g_off[NBIN + 1];
__device__ int   g_cur[NBIN];
__device__ int   g_ent[NQT];

// ---------------------------------------------------------------------------
// helpers
// ---------------------------------------------------------------------------
__device__ __forceinline__ uint32_t smem_u32(const void* p) {
    return (uint32_t)__cvta_generic_to_shared(p);
}
__device__ __forceinline__ void ldsm4(uint32_t r[4], uint32_t a) {
    asm volatile("ldmatrix.sync.aligned.m8n8.x4.shared.b16 {%0,%1,%2,%3}, [%4];\n"
                 : "=r"(r[0]), "=r"(r[1]), "=r"(r[2]), "=r"(r[3]) : "r"(a));
}
__device__ __forceinline__ void mma_bf16(float c[4], const uint32_t a[4], const uint32_t b[2]) {
    asm volatile(
        "mma.sync.aligned.m16n8k16.row.col.f32.bf16.bf16.f32 "
        "{%0,%1,%2,%3}, {%4,%5,%6,%7}, {%8,%9}, {%0,%1,%2,%3};\n"
        : "+f"(c[0]), "+f"(c[1]), "+f"(c[2]), "+f"(c[3])
        : "r"(a[0]), "r"(a[1]), "r"(a[2]), "r"(a[3]), "r"(b[0]), "r"(b[1]));
}
__device__ __forceinline__ void split1(float x, __nv_bfloat16& h, __nv_bfloat16& l) {
    h = __float2bfloat16(x);
    l = __float2bfloat16(x - __bfloat162float(h));
}

// ---------------------------------------------------------------------------
// GEMM on pre-split bf16 planes.
// out[m,n] = sum_k (Ah+Al)[m,k] * (Bh+Bl)[n,k]   (3-term bf16 emulation)
// A row-major [m][lda], B row-major [n][ldb]. Block tile 128 x (32*NFRAG).
// 8 warps: 2 in m (64 rows each), 4 in n (8*NFRAG cols each). k-chunk 16.
// mode: 0 = permuted bf16-plane write for Q projection (g_Qh/g_Ql)
//       1 = plain fp32 (+bias)
//       2 = bf16-plane write (+ncol offset)
// qtsel: B k-offset = ((m0>>13)&3)*64 (per-head Wk^T slice for the Qt GEMM)
// vhat : blockIdx.z selects head: A += z*256 cols, B += z*64 rows,
//        out col offset z*64.
// ---------------------------------------------------------------------------
template <int NFRAG>
__global__ void __launch_bounds__(256, 1)
gemm_planes(const __nv_bfloat16* __restrict__ Ah, const __nv_bfloat16* __restrict__ Al,
            int lda,
            const __nv_bfloat16* __restrict__ Bh, const __nv_bfloat16* __restrict__ Bl,
            int ldb, int K,
            const float* __restrict__ bias,
            float* __restrict__ outf,
            __nv_bfloat16* __restrict__ oph, __nv_bfloat16* __restrict__ opl,
            int ldo, int mode, int qtsel, int vhat)
{
    constexpr int NT = 32 * NFRAG;                       // block n-tile
    __shared__ __align__(16) __nv_bfloat16 sAh[2][128][SP];
    __shared__ __align__(16) __nv_bfloat16 sAl[2][128][SP];
    __shared__ __align__(16) __nv_bfloat16 sBh[2][NT][SP];
    __shared__ __align__(16) __nv_bfloat16 sBl[2][NT][SP];

    const int m0   = blockIdx.x * 128;
    const int n0   = blockIdx.y * NT;
    const int tid  = threadIdx.x;
    const int lane = tid & 31;
    const int wid  = tid >> 5;
    const int wm   = (wid & 1) * 64;
    const int wn   = (wid >> 1) * (8 * NFRAG);

    int koff = qtsel ? ((m0 >> 13) & 3) * 64 : 0;
    const __nv_bfloat16* Ahp = Ah;
    const __nv_bfloat16* Alp = Al;
    const __nv_bfloat16* Bhp = Bh;
    const __nv_bfloat16* Blp = Bl;
    int ncol_off = 0;
    if (vhat) {
        const int hz = blockIdx.z;
        Ahp += hz * 256;  Alp += hz * 256;               // column offset (lda=1024)
        Bhp += (size_t)hz * 64 * ldb;  Blp += (size_t)hz * 64 * ldb;
        ncol_off = hz * 64;
    }

    // loaders: A 128x16 (256 thr), B NTx16 (2*NT thr)
    const int am = tid >> 1;
    const int ak = (tid & 1) << 3;
    const int bn = tid >> 1;                              // valid if tid < 2*NT
    const int bk = (tid & 1) << 3;
    const bool bact = (NFRAG == 4) || (tid < 2 * NT);

    // ldmatrix lane addressing (non-trans, A[m][k] 16x16 tiles)
    const int lrow = (lane & 7) + (lane & 8);
    const int lcol = (lane & 16) ? 8 : 0;
    // B frag addressing
    const int fn = lane >> 2;
    const int fc = (lane & 3) * 2;

    float acc[4][NFRAG][4];
#pragma unroll
    for (int i = 0; i < 4; i++)
#pragma unroll
        for (int j = 0; j < NFRAG; j++)
#pragma unroll
            for (int r = 0; r < 4; r++) acc[i][j][r] = 0.f;

    uint4 rah, ral, rbh, rbl;
    auto ldg_chunk = [&](int kc) {
        const int k0 = kc * 16;
        rah = *(const uint4*)&Ahp[(size_t)(m0 + am) * lda + k0 + ak];
        ral = *(const uint4*)&Alp[(size_t)(m0 + am) * lda + k0 + ak];
        if (bact) {
            rbh = *(const uint4*)&Bhp[(size_t)(n0 + bn) * ldb + koff + k0 + bk];
            rbl = *(const uint4*)&Blp[(size_t)(n0 + bn) * ldb + koff + k0 + bk];
        }
    };
    auto st_chunk = [&](int buf) {
        *(uint4*)&sAh[buf][am][ak] = rah;
        *(uint4*)&sAl[buf][am][ak] = ral;
        if (bact) {
            *(uint4*)&sBh[buf][bn][bk] = rbh;
            *(uint4*)&sBl[buf][bn][bk] = rbl;
        }
    };

    auto compute = [&](int buf) {
        uint32_t Ahf[4][4], Alf[4][4], Bhf[NFRAG][2], Blf[NFRAG][2];
#pragma unroll
        for (int mf = 0; mf < 4; mf++) {
            const int mr = wm + mf * 16 + lrow;
            ldsm4(Ahf[mf], smem_u32(&sAh[buf][mr][lcol]));
            ldsm4(Alf[mf], smem_u32(&sAl[buf][mr][lcol]));
        }
#pragma unroll
        for (int nf = 0; nf < NFRAG; nf++) {
            const int n = wn + nf * 8 + fn;
            Bhf[nf][0] = *(const uint32_t*)&sBh[buf][n][fc];
            Bhf[nf][1] = *(const uint32_t*)&sBh[buf][n][fc + 8];
            Blf[nf][0] = *(const uint32_t*)&sBl[buf][n][fc];
            Blf[nf][1] = *(const uint32_t*)&sBl[buf][n][fc + 8];
        }
#pragma unroll
        for (int mf = 0; mf < 4; mf++)
#pragma unroll
            for (int nf = 0; nf < NFRAG; nf++) {
                mma_bf16(acc[mf][nf], Ahf[mf], Bhf[nf]);
                mma_bf16(acc[mf][nf], Ahf[mf], Blf[nf]);
                mma_bf16(acc[mf][nf], Alf[mf], Bhf[nf]);
            }
    };

    const int NKC = K / 16;
    ldg_chunk(0);
    st_chunk(0);
    __syncthreads();

    for (int kc = 0; kc < NKC; kc++) {
        const int buf = kc & 1;
        if (kc + 1 < NKC) ldg_chunk(kc + 1);
        compute(buf);
        if (kc + 1 < NKC) {
            st_chunk(buf ^ 1);
            __syncthreads();
        }
    }

    // epilogue
#pragma unroll
    for (int mf = 0; mf < 4; mf++)
#pragma unroll
        for (int nf = 0; nf < NFRAG; nf++) {
            const int ncol = n0 + wn + nf * 8 + fc;
            const float bx = bias ? bias[ncol]     : 0.f;
            const float by = bias ? bias[ncol + 1] : 0.f;
#pragma unroll
            for (int half = 0; half < 2; half++) {
                const int mrow = m0 + wm + mf * 16 + (lane >> 2) + half * 8;
                const float ox = acc[mf][nf][half * 2]     + bx;
                const float oy = acc[mf][nf][half * 2 + 1] + by;
                if (mode == 0) {
                    // Q projection -> g_Q planes [B,H,NV,64]
                    const int bb = mrow >> 13;
                    const int nv = mrow & (NV_ - 1);
                    const int hh = ncol >> 6;
                    const int d  = ncol & 63;
                    const size_t idx = (((size_t)(bb * H_ + hh)) * NV_ + nv) * DH_ + d;
                    __nv_bfloat162 h2, l2;
                    split1(ox, h2.x, l2.x);
                    split1(oy, h2.y, l2.y);
                    *(__nv_bfloat162*)&oph[idx] = h2;
                    *(__nv_bfloat162*)&opl[idx] = l2;
                } else if (mode == 1) {
                    float2 o; o.x = ox; o.y = oy;
                    *(float2*)&outf[(size_t)mrow * ldo + ncol] = o;
                } else {
                    const size_t idx = (size_t)mrow * ldo + ncol_off + ncol;
                    __nv_bfloat162 h2, l2;
                    split1(ox, h2.x, l2.x);
                    split1(oy, h2.y, l2.y);
                    *(__nv_bfloat162*)&oph[idx] = h2;
                    *(__nv_bfloat162*)&opl[idx] = l2;
                }
            }
        }
}

// ---------------------------------------------------------------------------
// Precompute: split weights into bf16 planes (+ Wk transpose) + zero g_cnt
// ---------------------------------------------------------------------------
__global__ void split_weights(const float* __restrict__ Wq,
                              const float* __restrict__ Wk,
                              const float* __restrict__ Wv,
                              const float* __restrict__ Wo) {
    const int r = blockIdx.x;     // 256
    const int c = threadIdx.x;    // 256
    const int i = r * C_ + c;
    split1(Wq[i], g_Wqh[i], g_Wql[i]);
    split1(Wk[c * C_ + r], g_WkTh[i], g_WkTl[i]);   // WkT[r][c] = Wk[c][r]
    split1(Wv[i], g_Wvh[i], g_Wvl[i]);
    split1(Wo[i], g_Woh[i], g_Wol[i]);
    if (i < NBIN) g_cnt[i] = 0;
}

__global__ void split_qfeat(const float* __restrict__ qf) {
    const int t = blockIdx.x * 256 + threadIdx.x;   // 1M float4
    const float4 v = ((const float4*)qf)[t];
    __nv_bfloat16 h[4], l[4];
    split1(v.x, h[0], l[0]); split1(v.y, h[1], l[1]);
    split1(v.z, h[2], l[2]); split1(v.w, h[3], l[3]);
    *(uint2*)&g_qfh[(size_t)t * 4] = *(const uint2*)h;
    *(uint2*)&g_qfl[(size_t)t * 4] = *(const uint2*)l;
}

__global__ void btld_kernel(const float* __restrict__ Wo,
                            const float* __restrict__ bv,
                            const float* __restrict__ bo) {
    const int i = threadIdx.x;   // 256
    float s = bo[i];
    for (int j = 0; j < C_; j++) s = fmaf(Wo[(size_t)i * C_ + j], bv[j], s);
    g_btld[i] = s;
}

// ---------------------------------------------------------------------------
// Bucketing
// ---------------------------------------------------------------------------
__global__ void hist_kernel(const int* __restrict__ nidx) {
    const int t = blockIdx.x * 256 + threadIdx.x;   // 65536
    const int b = t >> 15;
    atomicAdd(&g_cnt[(b << 11) | nidx[t]], 1);
}

__global__ void scan_kernel() {
    __shared__ int tsum[1024];
    const int t = threadIdx.x;
    const int4 v = ((const int4*)g_cnt)[t];
    const int s0 = v.x, s01 = v.x + v.y, s012 = s01 + v.z;
    const int tot = s012 + v.w;
    tsum[t] = tot;
    __syncthreads();
    for (int off = 1; off < 1024; off <<= 1) {
        int x = (t >= off) ? tsum[t - off] : 0;
        __syncthreads();
        tsum[t] += x;
        __syncthreads();
    }
    const int base = tsum[t] - tot;
    g_off[4 * t]     = base;          g_cur[4 * t]     = base;
    g_off[4 * t + 1] = base + s0;     g_cur[4 * t + 1] = base + s0;
    g_off[4 * t + 2] = base + s01;    g_cur[4 * t + 2] = base + s01;
    g_off[4 * t + 3] = base + s012;   g_cur[4 * t + 3] = base + s012;
    if (t == 1023) g_off[NBIN] = tsum[1023];
}

__global__ void scatter_kernel(const int* __restrict__ nidx) {
    const int t = blockIdx.x * 256 + threadIdx.x;   // 65536
    const int b  = t >> 15;
    const int h  = (t >> 13) & 3;
    const int nv = t & (NV_ - 1);
    const int pos = atomicAdd(&g_cur[(b << 11) | nidx[t]], 1);
    g_ent[pos] = (h << 16) | nv;
}

// ---------------------------------------------------------------------------
// Bucketed attention. One CTA per (b,page). smem: (gf+kp) and gf pages,
// pad-33 rows. Per warp per query: scores over C=256, softmax over 32
// lanes, ghat -> g_Hat bf16 hi/lo planes [B,NV,H,256].
// ---------------------------------------------------------------------------
__global__ void __launch_bounds__(256)
attn_pages(const float* __restrict__ gf, const float* __restrict__ kp)
{
    extern __shared__ float sm[];
    float* ssum = sm;                    // [256][33]: gf+kp
    float* sgf  = sm + 256 * ROWP;       // [256][33]: gf

    const int bin  = blockIdx.x;
    const int b    = bin >> 11;
    const int page = bin & (NP2 - 1);
    const int off  = g_off[bin];
    const int cnt  = g_off[bin + 1] - off;
    if (cnt == 0) return;

    const int tid  = threadIdx.x;
    const int lane = tid & 31;
    const int w    = tid >> 5;

    const float* gfb = gf + (size_t)b * C_ * (NP2 * NS_) + page * NS_;
    const float* kpb = kp + (size_t)b * C_ * (NP2 * NS_) + page * NS_;

#pragma unroll
    for (int it = 0; it < 8; it++) {
        const int i = it * 256 + tid;      // 2048 float4 slots
        const int c = i >> 3;
        const int j = (i & 7) * 4;
        const float4 g = *(const float4*)(gfb + (size_t)c * (NP2 * NS_) + j);
        const float4 k = *(const float4*)(kpb + (size_t)c * (NP2 * NS_) + j);
        float* pg = sgf  + c * ROWP + j;
        float* ps = ssum + c * ROWP + j;
        pg[0] = g.x; pg[1] = g.y; pg[2] = g.z; pg[3] = g.w;
        ps[0] = g.x + k.x; ps[1] = g.y + k.y; ps[2] = g.z + k.z; ps[3] = g.w + k.w;
    }
    __syncthreads();

    for (int e = w; e < cnt; e += 8) {
        const int ent = g_ent[off + e];
        const int h   = ent >> 16;
        const int nv  = ent & 0xffff;
        const size_t qrow = ((size_t)(b * H_ + h)) * NV_ + nv;

        const float4 qa = *(const float4*)&g_Qt[qrow * C_ + lane * 8];
        const float4 qb = *(const float4*)&g_Qt[qrow * C_ + lane * 8 + 4];
        const float q[8] = {qa.x, qa.y, qa.z, qa.w, qb.x, qb.y, qb.z, qb.w};

        float sc = 0.f;
#pragma unroll 4
        for (int src = 0; src < 32; src++) {
#pragma unroll
            for (int j = 0; j < 8; j++) {
                const float qc = __shfl_sync(0xffffffffu, q[j], src);
                sc = fmaf(qc, ssum[(src * 8 + j) * ROWP + lane], sc);
            }
        }
        sc *= 0.125f;

        float mx = sc;
#pragma unroll
        for (int o = 16; o; o >>= 1) mx = fmaxf(mx, __shfl_xor_sync(0xffffffffu, mx, o));
        const float ex = __expf(sc - mx);
        float sum = ex;
#pragma unroll
        for (int o = 16; o; o >>= 1) sum += __shfl_xor_sync(0xffffffffu, sum, o);
        const float pr = ex / sum;

        float acc[8] = {0.f, 0.f, 0.f, 0.f, 0.f, 0.f, 0.f, 0.f};
#pragma unroll 8
        for (int s = 0; s < 32; s++) {
            const float a = __shfl_sync(0xffffffffu, pr, s);
#pragma unroll
            for (int k = 0; k < 8; k++)
                acc[k] = fmaf(a, sgf[(lane + 32 * k) * ROWP + s], acc[k]);
        }

        const size_t obase = (((size_t)(b * NV_ + nv)) * H_ + h) * C_;
#pragma unroll
        for (int k = 0; k < 8; k++) {
            __nv_bfloat16 hh, ll;
            split1(acc[k], hh, ll);
            g_Hth[obase + lane + 32 * k] = hh;
            g_Htl[obase + lane + 32 * k] = ll;
        }
    }
}

// ---------------------------------------------------------------------------
// Launch
// ---------------------------------------------------------------------------
extern "C" void kernel_launch(void* const* d_in, const int* in_sizes, int n_in,
                              void* d_out, int out_size)
{
    const float* q_feat     = (const float*)d_in[0];
    const float* group_feat = (const float*)d_in[1];
    const float* k_pos      = (const float*)d_in[2];
    const int*   nidx       = (const int*)  d_in[3];
    const float* Wq = (const float*)d_in[4];  const float* bq = (const float*)d_in[5];
    const float* Wk = (const float*)d_in[6];
    const float* Wv = (const float*)d_in[8];  const float* bv = (const float*)d_in[9];
    const float* Wo = (const float*)d_in[10]; const float* bo = (const float*)d_in[11];
    float* out = (float*)d_out;

    __nv_bfloat16 *qfh, *qfl, *Qh, *Ql, *Hth, *Htl, *vh, *vl;
    __nv_bfloat16 *Wqh, *Wql, *WkTh, *WkTl, *Wvh, *Wvl, *Woh, *Wol;
    float *Qt, *btld;
    cudaGetSymbolAddress((void**)&qfh, g_qfh);   cudaGetSymbolAddress((void**)&qfl, g_qfl);
    cudaGetSymbolAddress((void**)&Qh,  g_Qh);    cudaGetSymbolAddress((void**)&Ql,  g_Ql);
    cudaGetSymbolAddress((void**)&Hth, g_Hth);   cudaGetSymbolAddress((void**)&Htl, g_Htl);
    cudaGetSymbolAddress((void**)&vh,  g_vh);    cudaGetSymbolAddress((void**)&vl,  g_vl);
    cudaGetSymbolAddress((void**)&Wqh, g_Wqh);   cudaGetSymbolAddress((void**)&Wql, g_Wql);
    cudaGetSymbolAddress((void**)&WkTh, g_WkTh); cudaGetSymbolAddress((void**)&WkTl, g_WkTl);
    cudaGetSymbolAddress((void**)&Wvh, g_Wvh);   cudaGetSymbolAddress((void**)&Wvl, g_Wvl);
    cudaGetSymbolAddress((void**)&Woh, g_Woh);   cudaGetSymbolAddress((void**)&Wol, g_Wol);
    cudaGetSymbolAddress((void**)&Qt,  g_Qt);
    cudaGetSymbolAddress((void**)&btld, g_btld);

    const int attn_smem = 2 * 256 * ROWP * (int)sizeof(float);   // 67584
    cudaFuncSetAttribute(attn_pages, cudaFuncAttributeMaxDynamicSharedMemorySize,
                         attn_smem);

    // precompute + bucketing
    split_weights<<<256, 256>>>(Wq, Wk, Wv, Wo);
    split_qfeat<<<(MQ * C_ / 4) / 256, 256>>>(q_feat);
    btld_kernel<<<1, 256>>>(Wo, bv, bo);
    hist_kernel<<<NQT / 256, 256>>>(nidx);
    scan_kernel<<<1, 1024>>>();
    scatter_kernel<<<NQT / 256, 256>>>(nidx);

    // Q projection: q_feat @ Wq^T + bq -> g_Q planes [B,H,NV,64]   (mode 0)
    gemm_planes<4><<<dim3(MQ / 128, 2), 256>>>(
        qfh, qfl, C_, Wqh, Wql, C_, C_, bq, nullptr, Qh, Ql, 0, 0, 0, 0);
    // Q-tilde: g_Q @ WkT_h -> g_Qt fp32 [NQT,256]                  (mode 1, qtsel)
    gemm_planes<4><<<dim3(NQT / 128, 2), 256>>>(
        Qh, Ql, DH_, WkTh, WkTl, C_, DH_, nullptr, Qt, nullptr, nullptr, C_, 1, 1, 0);
    // bucketed attention -> g_Hat planes [B,NV,H,256]
    attn_pages<<<NBIN, 256, attn_smem>>>(group_feat, k_pos);
    // vhat: per-head ghat_h @ Wv_h^T -> v planes [MQ,256]          (mode 2, vhat)
    gemm_planes<2><<<dim3(MQ / 128, 1, H_), 256>>>(
        Hth, Htl, H_ * C_, Wvh, Wvl, C_, C_, nullptr, nullptr, vh, vl, C_, 2, 0, 1);
    // out: v @ Wo^T + btld -> d_out fp32                           (mode 1)
    gemm_planes<4><<<dim3(MQ / 128, 2), 256>>>(
        vh, vl, C_, Woh, Wol, C_, C_, btld, out, nullptr, nullptr, C_, 1, 0, 0);
}